// round 9
// baseline (speedup 1.0000x reference)
#include <cuda_runtime.h>

#define TN 400
#define PN 4000
#define NPG 152            // pred groups (one per SM pair of blocks)
#define NBLK (NPG*2)       // grid: (pred group) x (target half)
#define TPB 800            // 25 warps; 8 lanes per target x 200 targets
#define MAXP 28            // >= ceil(PN/NPG)+1
#define ROW 88             // floats per pred row in ptile
#define THALF 200          // targets per block

typedef unsigned long long ull;

__device__ __forceinline__ ull pk2(float lo, float hi) {
    ull r; asm("mov.b64 %0, {%1,%2};" : "=l"(r) : "f"(lo), "f"(hi)); return r;
}
__device__ __forceinline__ float2 u2f2(ull v) {
    float2 f; asm("mov.b64 {%0,%1}, %2;" : "=f"(f.x), "=f"(f.y) : "l"(v)); return f;
}
__device__ __forceinline__ ull padd2(ull a, ull b) {
    ull r; asm("add.rn.f32x2 %0, %1, %2;" : "=l"(r) : "l"(a), "l"(b)); return r;
}
__device__ __forceinline__ ull pfma2(ull a, ull b, ull c) {
    ull r; asm("fma.rn.f32x2 %0, %1, %2, %3;" : "=l"(r) : "l"(a), "l"(b), "l"(c)); return r;
}

// dynamic smem layout (floats):
//   stg  [0 .. 10600)                staged tkp for this block's 200 targets
//   sraw [10600 .. 10600+1488)       staged raw pred rows
//   ptile[12088 .. +MAXP*ROW)        preprocessed pred rows
#define STG_OFF   0
#define SRAW_OFF  10600
#define PTILE_OFF (10600 + 1488)
#define SMEM_FLOATS (PTILE_OFF + MAXP * ROW)
#define SMEM_BYTES  (SMEM_FLOATS * 4)

// ptile row (88 floats):
//   [12q .. 12q+9]  Zp pairs of kp quarter q (5 pairs; unused -> 0), +2 pad
//   [48..51]        {cp0, cp1, p0-p1, spp}
//   [52+8q .. +4]   Vp of quarter q (5 vals; unused -> 0), +3 pad

__global__ __launch_bounds__(TPB, 2)
void matcher_kernel(const float* __restrict__ logits,   // [PN,2]
                    const float* __restrict__ pkp,      // [PN,53]
                    const int*   __restrict__ tids,     // [TN]
                    const float* __restrict__ tkp,      // [TN,53]
                    const int*   __restrict__ nbp,      // scalar num_boxes
                    float*       __restrict__ out)      // [PN,TN]
{
    extern __shared__ __align__(16) float dsm[];
    float* stg   = dsm + STG_OFF;
    float* sraw  = dsm + SRAW_OFF;
    float* ptile = dsm + PTILE_OFF;

    const int pg = blockIdx.x >> 1;                 // pred group
    const int th = blockIdx.x & 1;                  // target half
    const int pbase = (pg * PN) / NPG;
    const int npred = ((pg + 1) * PN) / NPG - pbase;
    const int tbase = th * THALF;

    const int tid  = threadIdx.x;
    const int lane = tid & 31;
    const int kq   = lane >> 3;                     // kp quarter 0..3
    const int tl   = ((tid >> 5) << 3) | (lane & 7);  // local target 0..199
    const int tw   = tbase + tl;                    // global target

    int nbi = *nbp;
    float nb = (nbi > 0 && nbi < (1 << 20)) ? (float)nbi : *(const float*)nbp;
    const float inb = 1.0f / nb;

    // ---- coalesced staging ----
    {
        const float4* src = (const float4*)(tkp + tbase * 53);  // 10600 floats
        float4* dst = (float4*)stg;
        #pragma unroll
        for (int i = 0; i < 4; ++i) {
            int idx = tid + i * TPB;
            if (idx < 2650) dst[idx] = src[idx];
        }
        const int nraw = npred * 53;
        const float* ps = pkp + pbase * 53;
        for (int i = tid; i < nraw; i += TPB) sraw[i] = ps[i];
    }
    __syncthreads();

    // ---- pred preprocessing (threads 0..npred-1) ----
    if (tid < npred) {
        const int gp = pbase + tid;
        const float l0 = logits[gp * 2 + 0];
        const float l1 = logits[gp * 2 + 1];
        const float m  = fmaxf(l0, l1);
        const float e0 = __expf(l0 - m);
        const float e1 = __expf(l1 - m);
        const float inv = 1.0f / (e0 + e1);
        const float p0 = e0 * inv, p1 = e1 * inv;

        const float* kp = sraw + tid * 53;          // conflict-free (odd stride)
        const float c0 = kp[0], c1 = kp[1];
        float* sp = ptile + tid * ROW;
        #pragma unroll
        for (int q = 0; q < 4; ++q) {
            const int jbq  = q ? (4 * q + 1) : 0;
            const int cntq = q ? 4 : 5;
            #pragma unroll
            for (int i = 0; i < 5; ++i) {
                const int j = jbq + i;
                const bool ok = (i < cntq);
                sp[12 * q + 2 * i]     = ok ? kp[2 + 2 * j] : 0.0f;
                sp[12 * q + 2 * i + 1] = ok ? kp[3 + 2 * j] : 0.0f;
            }
            sp[12 * q + 10] = 0.0f;
            sp[12 * q + 11] = 0.0f;
            #pragma unroll
            for (int i = 0; i < 5; ++i)
                sp[52 + 8 * q + i] = (i < cntq) ? kp[36 + jbq + i] : 0.0f;
            sp[52 + 8 * q + 5] = 0.0f;
            sp[52 + 8 * q + 6] = 0.0f;
            sp[52 + 8 * q + 7] = 0.0f;
        }
        float sv = 0.0f;
        #pragma unroll
        for (int j = 0; j < 17; ++j) { float v = kp[36 + j]; sv = fmaf(v, v, sv); }
        sp[48] = c0;
        sp[49] = c1;
        sp[50] = p0 - p1;
        sp[51] = 0.2f * inb * sv + 0.5f * inb * (c0 * c0 + c1 * c1) - p0;  // spp
    }

    // ---- per-thread target state (5 kps of one quarter) ----
    const float* tk = stg + tl * 53;
    const float cg0 = tk[0], cg1 = tk[1];
    const int jbq  = kq ? (4 * kq + 1) : 0;
    const int cntq = kq ? 4 : 5;
    ull nzg[5];
    ull wd2[2];                // {0.5*inb*v_a, 0.5*inb*v_b} pairs
    ull wt;                    // 5th kp: {0.5w, 4w} (zero for quarters 1..3)
    #pragma unroll
    for (int i = 0; i < 5; ++i) {
        const int j = jbq + i;
        nzg[i] = (i < cntq) ? pk2(-tk[2 + 2 * j], -tk[3 + 2 * j]) : 0ULL;
    }
    wd2[0] = pk2(0.5f * inb * tk[36 + jbq],     0.5f * inb * tk[36 + jbq + 1]);
    wd2[1] = pk2(0.5f * inb * tk[36 + jbq + 2], 0.5f * inb * tk[36 + jbq + 3]);
    {
        float v4 = (cntq == 5) ? tk[36 + jbq + 4] : 0.0f;
        wt = pk2(0.5f * inb * v4, 4.0f * inb * v4);
    }
    const float ncgx = -cg0, ncgy = -cg1;
    float tcx = 0.0f, tcy = 0.0f, idf = 0.0f, sgt = 0.0f, cflag = 0.0f;
    if (kq == 0) {
        float sv = 0.0f;
        #pragma unroll
        for (int j = 0; j < 17; ++j) { float v = tk[36 + j]; sv = fmaf(v, v, sv); }
        sgt = 0.2f * inb * sv + 0.5f * inb * (cg0 * cg0 + cg1 * cg1);
        tcx = -inb * cg0;
        tcy = -inb * cg1;
        idf = (float)tids[tw];
        cflag = 1.0f;
    }
    __syncthreads();

    const bool doStore = (kq == 0);
    const float* pp = ptile + 12 * kq;   // this quarter's Zp base
    const int voff = 52 + 8 * kq;

    for (int p = 0; p < npred; ++p, pp += ROW) {
        const float4 h4 = *(const float4*)(pp + (48 - 12 * kq));  // row base + 48
        const ull dc2 = pk2(h4.x + ncgx, h4.y + ncgy);

        const ulonglong2* z2 = (const ulonglong2*)pp;
        ull acw = 0ULL;   // {even-kp offset sums, odd-kp offset sums} (+tail)
        ull ac8 = 0ULL;   // abs sums (x8 folded at end)
        #pragma unroll
        for (int q = 0; q < 2; ++q) {
            ulonglong2 z = z2[q];                   // LDS.128: kp 2q, 2q+1
            ull dz0 = padd2(z.x, nzg[2 * q]);
            ull t0  = padd2(dz0, dc2);
            ull dz1 = padd2(z.y, nzg[2 * q + 1]);
            ull t1  = padd2(dz1, dc2);
            float2 d0 = u2f2(dz0), u0 = u2f2(t0);
            float2 d1 = u2f2(dz1), u1 = u2f2(t1);
            float a00 = fabsf(d0.x) + fabsf(d0.y);
            float a01 = fabsf(d1.x) + fabsf(d1.y);
            float a10 = fabsf(u0.x) + fabsf(u0.y);
            float a11 = fabsf(u1.x) + fabsf(u1.y);
            acw = pfma2(pk2(a00, a01), wd2[q], acw);
            ac8 = pfma2(pk2(a10, a11), wd2[q], ac8);
        }
        {   // 5th keypoint (zero-padded for quarters 1..3)
            ull z4 = ((const ull*)pp)[4];           // LDS.64
            ull dz = padd2(z4, nzg[4]);
            ull t  = padd2(dz, dc2);
            float2 d = u2f2(dz), u = u2f2(t);
            float a0 = fabsf(d.x) + fabsf(d.y);
            float a1 = fabsf(u.x) + fabsf(u.y);
            acw = pfma2(pk2(a0, a1), wt, acw);      // {0.5w*a0, 4w*a1}
        }

        // viz dot for this quarter
        const float* vb = pp + (voff - 12 * kq);    // row base + voff
        const ulonglong2 vv = *(const ulonglong2*)vb;
        ull dv2 = pfma2(vv.x, wd2[0], 0ULL);
        dv2 = pfma2(vv.y, wd2[1], dv2);
        float2 dvf = u2f2(dv2);
        float dv = fmaf(vb[4], u2f2(wt).x, dvf.x + dvf.y);

        float2 aw = u2f2(acw), a8 = u2f2(ac8);
        float res = aw.x + aw.y;
        res = fmaf(a8.x + a8.y, 8.0f, res);
        res = fmaf(dv, -0.8f, res);
        res = fmaf(h4.x, tcx, res);
        res = fmaf(h4.y, tcy, res);
        res = fmaf(h4.z, idf, res);
        res = fmaf(h4.w, cflag, res);
        res += sgt;

        res += __shfl_xor_sync(0xffffffffu, res, 8);
        res += __shfl_xor_sync(0xffffffffu, res, 16);

        if (doStore)
            out[(size_t)(pbase + p) * TN + tw] = res;
    }
}

extern "C" void kernel_launch(void* const* d_in, const int* in_sizes, int n_in,
                              void* d_out, int out_size)
{
    const float* logits = (const float*)d_in[0];   // pred_logits   [8,500,2]
    const float* pkp    = (const float*)d_in[1];   // pred_keypoints[8,500,53]
    const int*   tids   = (const int*)  d_in[2];   // tgt_ids       [400]
    const float* tkp    = (const float*)d_in[3];   // tgt_keypoints [400,53]
    const int*   nbp    = (const int*)  d_in[4];   // num_boxes scalar
    (void)in_sizes; (void)n_in; (void)out_size;

    static int smem_set = 0;
    if (!smem_set) {
        cudaFuncSetAttribute(matcher_kernel,
                             cudaFuncAttributeMaxDynamicSharedMemorySize, SMEM_BYTES);
        smem_set = 1;
    }
    matcher_kernel<<<NBLK, TPB, SMEM_BYTES>>>(logits, pkp, tids, tkp, nbp,
                                              (float*)d_out);
}

// round 10
// speedup vs baseline: 1.6747x; 1.6747x over previous
#include <cuda_runtime.h>

#define TN 400
#define PN 4000
#define NBLOCKS 152       // one block per GB300 SM
#define TPB 800           // 25 warps x 16 targets = 400, all lanes active
#define MAXP 28           // >= ceil(PN/NBLOCKS)+1
#define ROW 72            // floats per pred row in ptile

typedef unsigned long long ull;

__device__ __forceinline__ ull pk2(float lo, float hi) {
    ull r; asm("mov.b64 %0, {%1,%2};" : "=l"(r) : "f"(lo), "f"(hi)); return r;
}
__device__ __forceinline__ float2 u2f2(ull v) {
    float2 f; asm("mov.b64 {%0,%1}, %2;" : "=f"(f.x), "=f"(f.y) : "l"(v)); return f;
}
__device__ __forceinline__ ull padd2(ull a, ull b) {
    ull r; asm("add.rn.f32x2 %0, %1, %2;" : "=l"(r) : "l"(a), "l"(b)); return r;
}
__device__ __forceinline__ ull pfma2(ull a, ull b, ull c) {
    ull r; asm("fma.rn.f32x2 %0, %1, %2, %3;" : "=l"(r) : "l"(a), "l"(b), "l"(c)); return r;
}

// dynamic smem layout (floats):
//   stg  [0 .. 21200)                staged tkp (400 x 53)
//   sraw [21200 .. 21200+1488)       staged raw pred rows
//   ptile[22688 .. +MAXP*ROW)        preprocessed pred rows
#define STG_OFF   0
#define SRAW_OFF  21200
#define PTILE_OFF (21200 + 1488)
#define SMEM_FLOATS (PTILE_OFF + MAXP * ROW)
#define SMEM_BYTES  (SMEM_FLOATS * 4)

__global__ __launch_bounds__(TPB, 1)
void matcher_kernel(const float* __restrict__ logits,   // [PN,2]
                    const float* __restrict__ pkp,      // [PN,53]
                    const int*   __restrict__ tids,     // [TN]
                    const float* __restrict__ tkp,      // [TN,53]
                    const int*   __restrict__ nbp,      // scalar num_boxes
                    float*       __restrict__ out)      // [PN,TN]
{
    extern __shared__ __align__(16) float dsm[];
    float* stg   = dsm + STG_OFF;
    float* sraw  = dsm + SRAW_OFF;
    float* ptile = dsm + PTILE_OFF;

    const int b = blockIdx.x;
    const int pbase = (b * PN) / NBLOCKS;
    const int npred = ((b + 1) * PN) / NBLOCKS - pbase;
    const int tid  = threadIdx.x;
    const int lane = tid & 31;
    const int h    = lane >> 4;                       // keypoint half
    const int tw   = ((tid >> 5) << 4) | (lane & 15); // target 0..399

    int nbi = *nbp;
    float nb = (nbi > 0 && nbi < (1 << 20)) ? (float)nbi : *(const float*)nbp;
    const float inb = 1.0f / nb;

    // ---- coalesced staging: targets (float4) + this block's raw preds ----
    {
        const float4* src = (const float4*)tkp;       // 21200 floats = 5300 float4
        float4* dst = (float4*)stg;
        #pragma unroll
        for (int i = 0; i < 7; ++i) {
            int idx = tid + i * TPB;
            if (idx < 5300) dst[idx] = src[idx];
        }
        const int nraw = npred * 53;
        const float* ps = pkp + pbase * 53;
        for (int i = tid; i < nraw; i += TPB) sraw[i] = ps[i];
    }
    __syncthreads();

    // ---- ptile fill, parallel across ALL threads (pure data movement) ----
    {
        const int total = npred * ROW;
        for (int idx = tid; idx < total; idx += TPB) {
            const int r = idx / ROW;
            const int s = idx - r * ROW;
            const float* kp = sraw + r * 53;
            float v = 0.0f;
            if (s < 18)                 v = kp[2 + s];        // Zp kp0..8
            else if (s >= 20 && s < 36) v = kp[s];            // Zp kp9..16
            else if (s >= 44 && s < 53) v = kp[s - 8];        // Vp0..8
            else if (s >= 56 && s < 64) v = kp[s - 11];       // Vp9..16
            if (s < 40 && s >= 36) continue;                  // scalar slots
            ptile[r * ROW + s] = v;
        }
    }
    // ---- per-pred scalars (threads 0..npred-1 only) ----
    if (tid < npred) {
        const int gp = pbase + tid;
        const float l0 = logits[gp * 2 + 0];
        const float l1 = logits[gp * 2 + 1];
        const float m  = fmaxf(l0, l1);
        const float e0 = __expf(l0 - m);
        const float e1 = __expf(l1 - m);
        const float inv = 1.0f / (e0 + e1);
        const float p0 = e0 * inv, p1 = e1 * inv;

        const float* kp = sraw + tid * 53;
        const float c0 = kp[0], c1 = kp[1];
        float sv = 0.0f;
        #pragma unroll
        for (int j = 0; j < 17; ++j) { float v = kp[36 + j]; sv = fmaf(v, v, sv); }
        float* sp = ptile + tid * ROW;
        sp[40] = c0;
        sp[41] = c1;
        sp[42] = p0 - p1;
        sp[43] = 0.2f * inb * sv + 0.5f * inb * (c0 * c0 + c1 * c1) - p0;  // spp
    }

    // ---- per-thread target state from staged smem (conflict-free LDS) ----
    const float* tk = stg + tw * 53;
    const float cg0 = tk[0], cg1 = tk[1];
    const int jb  = h ? 9 : 0;
    const int cnt = h ? 8 : 9;
    ull nzg[9];
    ull wd2[4];                // {0.5w_2q, 0.5w_2q+1}, w_j = inb*Vg_j
    ull wt;                    // tail kp: {0.5w_8, 4w_8}
    #pragma unroll
    for (int i = 0; i < 9; ++i) {
        const int j = jb + i;
        nzg[i] = (i < cnt) ? pk2(-tk[2 + 2 * j], -tk[3 + 2 * j]) : 0ULL;
    }
    #pragma unroll
    for (int q = 0; q < 4; ++q) {
        float va = tk[36 + jb + 2 * q];
        float vb = tk[36 + jb + 2 * q + 1];
        wd2[q] = pk2(0.5f * inb * va, 0.5f * inb * vb);
    }
    {
        float v8 = (cnt == 9) ? tk[36 + jb + 8] : 0.0f;
        wt = pk2(0.5f * inb * v8, 4.0f * inb * v8);
    }
    const float ncgx = -cg0, ncgy = -cg1;
    float tcx = 0.0f, tcy = 0.0f, idf = 0.0f, sgt = 0.0f, cflag = 0.0f;
    if (h == 0) {
        float sv = 0.0f;
        #pragma unroll
        for (int j = 0; j < 17; ++j) { float v = tk[36 + j]; sv = fmaf(v, v, sv); }
        sgt = 0.2f * inb * sv + 0.5f * inb * (cg0 * cg0 + cg1 * cg1);
        tcx = -inb * cg0;
        tcy = -inb * cg1;
        idf = (float)tids[tw];
        cflag = 1.0f;
    }
    __syncthreads();

    const int zbase = h ? 10 : 0;       // ull index of this half's Zp
    const int vbase = h ? 56 : 44;      // float index of this half's Vp
    const bool doStore = (h == 0);

    auto compute = [&](const float* pp) -> float {
        const float4 h4 = *(const float4*)(pp + 40);   // cp0, cp1, p0-p1, spp
        const ull dc2 = pk2(h4.x + ncgx, h4.y + ncgy); // (Cp-Cg) per axis

        const ulonglong2* z2 = (const ulonglong2*)((const ull*)pp + zbase);
        ull acw = 0ULL;    // per-lane: offset sums even/odd kp (tail merged)
        ull ac8 = 0ULL;    // per-lane: abs sums (x8 folded at the end)
        #pragma unroll
        for (int q = 0; q < 4; ++q) {
            ulonglong2 z = z2[q];                       // LDS.128: kp 2q, 2q+1
            ull dz0 = padd2(z.x, nzg[2 * q]);
            ull t0  = padd2(dz0, dc2);
            ull dz1 = padd2(z.y, nzg[2 * q + 1]);
            ull t1  = padd2(dz1, dc2);
            float2 d0 = u2f2(dz0), u0 = u2f2(t0);
            float2 d1 = u2f2(dz1), u1 = u2f2(t1);
            float a00 = fabsf(d0.x) + fabsf(d0.y);      // FADD w/ abs modifiers
            float a01 = fabsf(d1.x) + fabsf(d1.y);
            float a10 = fabsf(u0.x) + fabsf(u0.y);
            float a11 = fabsf(u1.x) + fabsf(u1.y);
            acw = pfma2(pk2(a00, a01), wd2[q], acw);
            ac8 = pfma2(pk2(a10, a11), wd2[q], ac8);
        }
        {   // tail keypoint 8 (pad zeros for half 1)
            ull z8 = ((const ull*)pp)[zbase + 8];       // LDS.64
            ull dz = padd2(z8, nzg[8]);
            ull t  = padd2(dz, dc2);
            float2 d = u2f2(dz), u = u2f2(t);
            float a0 = fabsf(d.x) + fabsf(d.y);
            float a1 = fabsf(u.x) + fabsf(u.y);
            acw = pfma2(pk2(a0, a1), wt, acw);          // {0.5w8*a0, 4w8*a1}
        }

        // viz dot, packed with the same wd2 weights
        const ulonglong2* vv = (const ulonglong2*)(pp + vbase);
        ulonglong2 va = vv[0], vbq = vv[1];             // Vp pairs 0..7
        ull dv2 = pfma2(va.x,  wd2[0], 0ULL);
        dv2 = pfma2(va.y,  wd2[1], dv2);
        dv2 = pfma2(vbq.x, wd2[2], dv2);
        dv2 = pfma2(vbq.y, wd2[3], dv2);
        float2 dvf = u2f2(dv2);
        float dv = dvf.x + dvf.y;
        dv = fmaf(pp[vbase + 8], u2f2(wt).x, dv);       // tail Vp8 * 0.5w8

        float2 aw = u2f2(acw), a8 = u2f2(ac8);
        float res = aw.x + aw.y;                        // offset + tail terms
        res = fmaf(a8.x + a8.y, 8.0f, res);             // abs terms (4w = 8*0.5w)
        res = fmaf(dv, -0.8f, res);                     // viz cross
        res = fmaf(h4.x, tcx, res);                     // center cross x (half0)
        res = fmaf(h4.y, tcy, res);                     // center cross y
        res = fmaf(h4.z, idf, res);                     // class id*(p0-p1)
        res = fmaf(h4.w, cflag, res);                   // pred constant (incl -p0)
        return res + sgt;                               // target constant
    };

    int p = 0;
    for (; p + 2 < npred; p += 3) {
        float r0 = compute(ptile + p * ROW);
        float r1 = compute(ptile + (p + 1) * ROW);
        float r2 = compute(ptile + (p + 2) * ROW);
        r0 += __shfl_xor_sync(0xffffffffu, r0, 16);
        r1 += __shfl_xor_sync(0xffffffffu, r1, 16);
        r2 += __shfl_xor_sync(0xffffffffu, r2, 16);
        if (doStore) {
            float* o = out + (size_t)(pbase + p) * TN + tw;
            o[0]      = r0;
            o[TN]     = r1;
            o[2 * TN] = r2;
        }
    }
    for (; p < npred; ++p) {
        float r0 = compute(ptile + p * ROW);
        r0 += __shfl_xor_sync(0xffffffffu, r0, 16);
        if (doStore)
            out[(size_t)(pbase + p) * TN + tw] = r0;
    }
}

extern "C" void kernel_launch(void* const* d_in, const int* in_sizes, int n_in,
                              void* d_out, int out_size)
{
    const float* logits = (const float*)d_in[0];   // pred_logits   [8,500,2]
    const float* pkp    = (const float*)d_in[1];   // pred_keypoints[8,500,53]
    const int*   tids   = (const int*)  d_in[2];   // tgt_ids       [400]
    const float* tkp    = (const float*)d_in[3];   // tgt_keypoints [400,53]
    const int*   nbp    = (const int*)  d_in[4];   // num_boxes scalar
    (void)in_sizes; (void)n_in; (void)out_size;

    static int smem_set = 0;
    if (!smem_set) {
        cudaFuncSetAttribute(matcher_kernel,
                             cudaFuncAttributeMaxDynamicSharedMemorySize, SMEM_BYTES);
        smem_set = 1;
    }
    matcher_kernel<<<NBLOCKS, TPB, SMEM_BYTES>>>(logits, pkp, tids, tkp, nbp,
                                                 (float*)d_out);
}

// round 11
// speedup vs baseline: 1.8816x; 1.1235x over previous
#include <cuda_runtime.h>
#include <cuda_fp16.h>

#define TN 400
#define PN 4000
#define NBLOCKS 152       // one block per GB300 SM
#define TPB 800           // 25 warps x 16 targets = 400, all lanes active
#define MAXP 28           // >= ceil(PN/NBLOCKS)+1
#define ROW 44            // floats per pred row in ptile

// dynamic smem layout (floats):
//   stg  [0 .. 21200)                staged tkp (400 x 53), fp32
//   sraw [21200 .. 21200+1488)       staged raw pred rows, fp32
//   ptile[22688 .. +MAXP*ROW)        preprocessed pred rows (half2 + fp32 scalars)
#define STG_OFF   0
#define SRAW_OFF  21200
#define PTILE_OFF (21200 + 1488)
#define SMEM_FLOATS (PTILE_OFF + MAXP * ROW)
#define SMEM_BYTES  (SMEM_FLOATS * 4)

// ptile row (44 x 32-bit slots):
//   u[0..8]   half2 Zp kp0..8 (x,y)      u[9..11]  0
//   u[12..20] half2 Zp kp9..16 + pad     u[21..23] 0
//   u[24..28] half2 Vp pairs h0 {(0,1)..(6,7),(8,0)}   u[29..31] 0
//   u[32..36] half2 Vp pairs h1 {(9,10)..(15,16),(0,0)} u[37..39] 0
//   f[40..43] fp32 {cp0, cp1, p0-p1, spp}

__device__ __forceinline__ __half2 u2h(unsigned u) {
    __half2 h; *reinterpret_cast<unsigned*>(&h) = u; return h;
}
__device__ __forceinline__ unsigned h2u(__half2 h) {
    return *reinterpret_cast<unsigned*>(&h);
}

__global__ __launch_bounds__(TPB, 1)
void matcher_kernel(const float* __restrict__ logits,   // [PN,2]
                    const float* __restrict__ pkp,      // [PN,53]
                    const int*   __restrict__ tids,     // [TN]
                    const float* __restrict__ tkp,      // [TN,53]
                    const int*   __restrict__ nbp,      // scalar num_boxes
                    float*       __restrict__ out)      // [PN,TN]
{
    extern __shared__ __align__(16) float dsm[];
    float* stg   = dsm + STG_OFF;
    float* sraw  = dsm + SRAW_OFF;
    float* ptile = dsm + PTILE_OFF;

    const int b = blockIdx.x;
    const int pbase = (b * PN) / NBLOCKS;
    const int npred = ((b + 1) * PN) / NBLOCKS - pbase;
    const int tid  = threadIdx.x;
    const int lane = tid & 31;
    const int h    = lane >> 4;                       // keypoint half
    const int tw   = ((tid >> 5) << 4) | (lane & 15); // target 0..399

    int nbi = *nbp;
    float nb = (nbi > 0 && nbi < (1 << 20)) ? (float)nbi : *(const float*)nbp;
    const float inb = 1.0f / nb;

    // ---- coalesced staging: targets (float4) + this block's raw preds ----
    {
        const float4* src = (const float4*)tkp;       // 21200 floats = 5300 float4
        float4* dst = (float4*)stg;
        #pragma unroll
        for (int i = 0; i < 7; ++i) {
            int idx = tid + i * TPB;
            if (idx < 5300) dst[idx] = src[idx];
        }
        const int nraw = npred * 53;
        const float* ps = pkp + pbase * 53;
        for (int i = tid; i < nraw; i += TPB) sraw[i] = ps[i];
    }
    __syncthreads();

    // ---- ptile fill (fp32 -> half2), parallel across all threads ----
    {
        const int total = npred * ROW;
        for (int idx = tid; idx < total; idx += TPB) {
            const int r = idx / ROW;
            const int s = idx - r * ROW;
            if (s >= 40) continue;                    // fp32 scalar slots
            const float* kp = sraw + r * 53;
            unsigned val = 0u;
            if (s < 9) {                              // h0 Zp: kp j=s
                val = h2u(__floats2half2_rn(kp[2 + 2 * s], kp[3 + 2 * s]));
            } else if (s >= 12 && s < 20) {           // h1 Zp: kp j=s-3 (9..16)
                const int j = s - 3;
                val = h2u(__floats2half2_rn(kp[2 + 2 * j], kp[3 + 2 * j]));
            } else if (s >= 24 && s < 28) {           // h0 Vp pairs (2i,2i+1)
                const int i = s - 24;
                val = h2u(__floats2half2_rn(kp[36 + 2 * i], kp[37 + 2 * i]));
            } else if (s == 28) {                     // (V8, 0)
                val = h2u(__floats2half2_rn(kp[44], 0.0f));
            } else if (s >= 32 && s < 36) {           // h1 Vp pairs (9+2i,10+2i)
                const int i = s - 32;
                val = h2u(__floats2half2_rn(kp[45 + 2 * i], kp[46 + 2 * i]));
            }
            ((unsigned*)(ptile + r * ROW))[s] = val;
        }
    }
    // ---- per-pred fp32 scalars (threads 0..npred-1) ----
    if (tid < npred) {
        const int gp = pbase + tid;
        const float l0 = logits[gp * 2 + 0];
        const float l1 = logits[gp * 2 + 1];
        const float m  = fmaxf(l0, l1);
        const float e0 = __expf(l0 - m);
        const float e1 = __expf(l1 - m);
        const float inv = 1.0f / (e0 + e1);
        const float p0 = e0 * inv, p1 = e1 * inv;

        const float* kp = sraw + tid * 53;
        const float c0 = kp[0], c1 = kp[1];
        float sv = 0.0f;
        #pragma unroll
        for (int j = 0; j < 17; ++j) { float v = kp[36 + j]; sv = fmaf(v, v, sv); }
        float* sp = ptile + tid * ROW;
        sp[40] = c0;
        sp[41] = c1;
        sp[42] = p0 - p1;
        sp[43] = 0.2f * inb * sv + 0.5f * inb * (c0 * c0 + c1 * c1) - p0;  // spp
    }

    // ---- per-thread target state (half2), from staged smem ----
    const float* tk = stg + tw * 53;
    const float cg0 = tk[0], cg1 = tk[1];
    const int jb  = h ? 9 : 0;
    const int cnt = h ? 8 : 9;
    __half2 nzg[9];            // {-Zg_x, -Zg_y} per kp
    __half2 w2[9];             // {0.5*inb*Vg, same}
    __half2 wv2[5];            // viz pairs {w_2i, w_2i+1}
    float wj[9];
    #pragma unroll
    for (int i = 0; i < 9; ++i) {
        const int j = jb + i;
        const bool ok = (i < cnt);
        nzg[i] = ok ? __floats2half2_rn(-tk[2 + 2 * j], -tk[3 + 2 * j])
                    : __floats2half2_rn(0.0f, 0.0f);
        wj[i]  = ok ? 0.5f * inb * tk[36 + j] : 0.0f;
        w2[i]  = __half2half2(__float2half_rn(wj[i]));
    }
    #pragma unroll
    for (int i = 0; i < 5; ++i)
        wv2[i] = __floats2half2_rn(wj[2 * i], (2 * i + 1 < 9) ? wj[2 * i + 1] : 0.0f);
    const __half2 eight2 = __half2half2(__float2half_rn(8.0f));
    const float ncgx = -cg0, ncgy = -cg1;
    float tcx = 0.0f, tcy = 0.0f, idf = 0.0f, sgt = 0.0f, cflag = 0.0f;
    if (h == 0) {
        float sv = 0.0f;
        #pragma unroll
        for (int j = 0; j < 17; ++j) { float v = tk[36 + j]; sv = fmaf(v, v, sv); }
        sgt = 0.2f * inb * sv + 0.5f * inb * (cg0 * cg0 + cg1 * cg1);
        tcx = -inb * cg0;
        tcy = -inb * cg1;
        idf = (float)tids[tw];
        cflag = 1.0f;
    }
    __syncthreads();

    const int zoff = h ? 12 : 0;
    const int voff = h ? 32 : 24;
    const bool doStore = (h == 0);

    auto compute = [&](const float* pp) -> float {
        const unsigned* ru = (const unsigned*)pp;
        const float4 h4 = *(const float4*)(pp + 40);   // cp0, cp1, p0-p1, spp
        const __half2 dch = __floats2half2_rn(h4.x + ncgx, h4.y + ncgy);

        const uint4 zA = *(const uint4*)(ru + zoff);       // LDS.128: kp 0..3
        const uint4 zB = *(const uint4*)(ru + zoff + 4);   // LDS.128: kp 4..7
        const unsigned z8 = ru[zoff + 8];                  // LDS.32 : kp 8

        __half2 acc = __floats2half2_rn(0.0f, 0.0f);
        #define KP(zr, i) do {                                            \
            __half2 z  = u2h(zr);                                         \
            __half2 dz = __hadd2(z, nzg[i]);                              \
            __half2 t  = __hadd2(dz, dch);                                \
            __half2 c  = __hfma2(__habs2(t), eight2, __habs2(dz));        \
            acc = __hfma2(c, w2[i], acc);                                 \
        } while (0)
        KP(zA.x, 0); KP(zA.y, 1); KP(zA.z, 2); KP(zA.w, 3);
        KP(zB.x, 4); KP(zB.y, 5); KP(zB.z, 6); KP(zB.w, 7);
        KP(z8,   8);
        #undef KP

        // viz dot in half2
        const uint4 vA = *(const uint4*)(ru + voff);
        const unsigned v8u = ru[voff + 4];
        __half2 dva = __hmul2(u2h(vA.x), wv2[0]);
        dva = __hfma2(u2h(vA.y), wv2[1], dva);
        dva = __hfma2(u2h(vA.z), wv2[2], dva);
        dva = __hfma2(u2h(vA.w), wv2[3], dva);
        dva = __hfma2(u2h(v8u),  wv2[4], dva);

        const float2 accf = __half22float2(acc);
        const float2 dvf  = __half22float2(dva);
        float res = accf.x + accf.y;              // 0.5*offset + 4*abs terms
        res = fmaf(dvf.x + dvf.y, -0.8f, res);    // viz cross
        res = fmaf(h4.x, tcx, res);               // center cross x (half0 only)
        res = fmaf(h4.y, tcy, res);               // center cross y
        res = fmaf(h4.z, idf, res);               // class id*(p0-p1)
        res = fmaf(h4.w, cflag, res);             // pred constant (incl -p0)
        return res + sgt;                         // target constant
    };

    int p = 0;
    for (; p + 2 < npred; p += 3) {
        float r0 = compute(ptile + p * ROW);
        float r1 = compute(ptile + (p + 1) * ROW);
        float r2 = compute(ptile + (p + 2) * ROW);
        r0 += __shfl_xor_sync(0xffffffffu, r0, 16);
        r1 += __shfl_xor_sync(0xffffffffu, r1, 16);
        r2 += __shfl_xor_sync(0xffffffffu, r2, 16);
        if (doStore) {
            float* o = out + (size_t)(pbase + p) * TN + tw;
            o[0]      = r0;
            o[TN]     = r1;
            o[2 * TN] = r2;
        }
    }
    for (; p < npred; ++p) {
        float r0 = compute(ptile + p * ROW);
        r0 += __shfl_xor_sync(0xffffffffu, r0, 16);
        if (doStore)
            out[(size_t)(pbase + p) * TN + tw] = r0;
    }
}

extern "C" void kernel_launch(void* const* d_in, const int* in_sizes, int n_in,
                              void* d_out, int out_size)
{
    const float* logits = (const float*)d_in[0];   // pred_logits   [8,500,2]
    const float* pkp    = (const float*)d_in[1];   // pred_keypoints[8,500,53]
    const int*   tids   = (const int*)  d_in[2];   // tgt_ids       [400]
    const float* tkp    = (const float*)d_in[3];   // tgt_keypoints [400,53]
    const int*   nbp    = (const int*)  d_in[4];   // num_boxes scalar
    (void)in_sizes; (void)n_in; (void)out_size;

    static int smem_set = 0;
    if (!smem_set) {
        cudaFuncSetAttribute(matcher_kernel,
                             cudaFuncAttributeMaxDynamicSharedMemorySize, SMEM_BYTES);
        smem_set = 1;
    }
    matcher_kernel<<<NBLOCKS, TPB, SMEM_BYTES>>>(logits, pkp, tids, tkp, nbp,
                                                 (float*)d_out);
}